// round 17
// baseline (speedup 1.0000x reference)
#include <cuda_runtime.h>
#include <cuda_fp16.h>

#define NN   100000
#define EE   1600000
#define ET   (EE + NN)     // 1,700,000
#define C    128
#define DIN  6
#define LINB ((NN * 64 + 255) / 256)   // 25000 lin blocks
#define ZB   ((NN + 255) / 256)        // 391 zero blocks

typedef unsigned long long ull;

// ---------------- device scratch ----------------
__device__ __half g_xl[NN * C];    // fp16 feature table (gathered by k_gat)
__device__ float  g_xr[NN * C];    // fp32 (coalesced per-node read)
__device__ __half g_h [NN * C];    // fp16 feature table (gathered by k_gemm)
__device__ float  g_ex[ET];        // CSR-ordered exp(logit)
__device__ float  g_alpha[ET];     // CSR-ordered alpha
__device__ uint4  g_csr[ET];       // (src, e0bits, e1bits, eid) — single STG.128
__device__ int    g_cnt[NN];
__device__ int    g_rowptr[NN + 1];
__device__ int    g_cur[NN];

// packed f32x2 helpers (Blackwell)
#define PK2(d, lo, hi)    asm("mov.b64 %0, {%1,%2};" : "=l"(d) : "f"(lo), "f"(hi))
#define UNPK2(lo, hi, s)  asm("mov.b64 {%0,%1}, %2;" : "=f"(lo), "=f"(hi) : "l"(s))
#define ADD2(d, a, b)     asm("add.rn.f32x2 %0, %1, %2;" : "=l"(d) : "l"(a), "l"(b))
#define MUL2(d, a, b)     asm("mul.rn.f32x2 %0, %1, %2;" : "=l"(d) : "l"(a), "l"(b))
#define FMA2D(d, a, b, c) asm("fma.rn.f32x2 %0, %1, %2, %3;" : "=l"(d) : "l"(a), "l"(b), "l"(c))
#define FMA2(d, a, b)     asm("fma.rn.f32x2 %0, %1, %2, %0;" : "+l"(d) : "l"(a), "l"(b))
#define AND64(d, a)       asm("and.b64 %0, %1, 0x7FFFFFFF7FFFFFFF;" : "=l"(d) : "l"(a))

// load 4 fp16 channels -> float4 (8 bytes)
__device__ __forceinline__ float4 ldh4(const __half* p) {
    uint2 u = *(const uint2*)p;
    __half2 h0, h1;
    *(unsigned*)&h0 = u.x; *(unsigned*)&h1 = u.y;
    float2 f0 = __half22float2(h0), f1 = __half22float2(h1);
    return make_float4(f0.x, f0.y, f1.x, f1.y);
}

// ---------------- K1: lin (blocks [0,LINB)) + zero g_cnt (blocks [LINB,LINB+ZB)) ----------------
__global__ void k_lin(const float* __restrict__ x,
                      const float* __restrict__ Wl, const float* __restrict__ bl,
                      const float* __restrict__ Wr, const float* __restrict__ br) {
    int b = blockIdx.x;
    if (b >= LINB) {
        int i = (b - LINB) * 256 + threadIdx.x;
        if (i < NN) g_cnt[i] = 0;
        return;
    }
    int idx = b * 256 + threadIdx.x;
    if (idx >= NN * 64) return;
    int n = idx >> 6, cp = (idx & 63) * 2;
    float a0 = bl[cp], a1 = bl[cp + 1];
    float b0 = br[cp], b1 = br[cp + 1];
#pragma unroll
    for (int k = 0; k < DIN; k++) {
        float xv = x[n * DIN + k];
        a0 += xv * Wl[k * C + cp];
        a1 += xv * Wl[k * C + cp + 1];
        b0 += xv * Wr[k * C + cp];
        b1 += xv * Wr[k * C + cp + 1];
    }
    ((__half2*)g_xl)[idx] = __floats2half2_rn(a0, a1);
    *(float2*)&g_xr[n * C + cp] = make_float2(b0, b1);
}

// ---------------- K2: histogram + src/dst stack output ----------------
__global__ void k_hist(const int* __restrict__ ei, float* __restrict__ out) {
    int e = blockIdx.x * blockDim.x + threadIdx.x;
    if (e >= ET) return;
    int s, d;
    if (e < EE) { s = ei[e]; d = ei[EE + e]; }
    else        { s = e - EE; d = s; }
    atomicAdd(&g_cnt[d], 1);
    out[NN * 2 + e]      = (float)s;
    out[NN * 2 + ET + e] = (float)d;
}

// ---------------- K3: exclusive scan ----------------
__global__ void k_scan() {
    __shared__ int ssum[1024];
    const int CH = (NN + 1023) / 1024;
    int t = threadIdx.x;
    int beg = t * CH; if (beg > NN) beg = NN;
    int end = beg + CH; if (end > NN) end = NN;
    int s = 0;
    for (int j = beg; j < end; j++) s += g_cnt[j];
    ssum[t] = s;
    __syncthreads();
    for (int off = 1; off < 1024; off <<= 1) {
        int v = (t >= off) ? ssum[t - off] : 0;
        __syncthreads();
        ssum[t] += v;
        __syncthreads();
    }
    int run = t ? ssum[t - 1] : 0;
    for (int j = beg; j < end; j++) {
        g_rowptr[j] = run;
        g_cur[j]    = run;
        run += g_cnt[j];
    }
    if (t == 0) g_rowptr[NN] = ET;
}

// ---------------- K4: scatter edges into CSR slots (single STG.128) ----------------
__global__ void k_scatter(const int* __restrict__ ei, const float* __restrict__ ew) {
    int e = blockIdx.x * blockDim.x + threadIdx.x;
    if (e >= ET) return;
    int s, d; float e0 = 0.f, e1 = 0.f;
    if (e < EE) {
        s = ei[e]; d = ei[EE + e];
        float2 v = *(const float2*)&ew[2 * e];
        e0 = v.x; e1 = v.y;
    } else { s = e - EE; d = s; }
    int pos = atomicAdd(&g_cur[d], 1);
    g_csr[pos] = make_uint4((unsigned)s, __float_as_uint(e0),
                            __float_as_uint(e1), (unsigned)e);
}

// packed logit for one edge's 4 channels on this lane; also emits packed a0,a1 for reuse
__device__ __forceinline__ float lane_logit_pk(uint2 u,
                                               ull xr0, ull xr1,
                                               ull e0p, ull e1p,
                                               ull w00, ull w01, ull w10, ull w11,
                                               ull at0, ull at1,
                                               ull c04, ull c06,
                                               ull& a0, ull& a1) {
    float2 f01 = __half22float2(*(__half2*)&u.x);
    float2 f23 = __half22float2(*(__half2*)&u.y);
    PK2(a0, f01.x, f01.y);
    PK2(a1, f23.x, f23.y);
    ull m, am, t, r, pacc;
    ADD2(m, a0, xr0);
    FMA2D(m, e0p, w00, m);
    FMA2D(m, e1p, w10, m);
    AND64(am, m);
    MUL2(t, am, c04);
    FMA2D(r, m, c06, t);              // leaky_relu(m, 0.2) = 0.6m + 0.4|m|
    MUL2(pacc, r, at0);
    ADD2(m, a1, xr1);
    FMA2D(m, e0p, w01, m);
    FMA2D(m, e1p, w11, m);
    AND64(am, m);
    MUL2(t, am, c04);
    FMA2D(r, m, c06, t);
    FMA2(pacc, r, at1);
    float plo, phi;
    UNPK2(plo, phi, pacc);
    return plo + phi;
}

// ---------------- K5: fused GATv2, single gather pass, packed f32x2 math ----------------
__global__ void __launch_bounds__(256, 4)
k_gat(const float* __restrict__ We, const float* __restrict__ att,
      const float* __restrict__ bgat, float* __restrict__ out) {
    int node = (blockIdx.x * blockDim.x + threadIdx.x) >> 5;
    int lane = threadIdx.x & 31;
    if (node >= NN) return;
    int c = lane * 4;

    ull w00, w01, w10, w11, at0, at1, xr0, xr1, c04, c06;
    {
        float4 A = *(const float4*)&We[c];
        PK2(w00, A.x, A.y); PK2(w01, A.z, A.w);
        A = *(const float4*)&We[C + c];
        PK2(w10, A.x, A.y); PK2(w11, A.z, A.w);
        A = *(const float4*)&att[c];
        PK2(at0, A.x, A.y); PK2(at1, A.z, A.w);
        A = *(const float4*)&g_xr[node * C + c];
        PK2(xr0, A.x, A.y); PK2(xr1, A.z, A.w);
    }
    PK2(c04, 0.4f, 0.4f);
    PK2(c06, 0.6f, 0.6f);

    int beg = g_rowptr[node], end = g_rowptr[node + 1];
    float den = 0.f;
    ull acc0 = 0ull, acc1 = 0ull;     // packed fp32 accumulators (0.0,0.0)

    int j = beg;
    for (; j + 3 < end; j += 4) {
        uint4 r0 = g_csr[j], r1 = g_csr[j + 1], r2 = g_csr[j + 2], r3 = g_csr[j + 3];
        uint2 u0 = *(const uint2*)&g_xl[r0.x * C + c];
        uint2 u1 = *(const uint2*)&g_xl[r1.x * C + c];
        uint2 u2 = *(const uint2*)&g_xl[r2.x * C + c];
        uint2 u3 = *(const uint2*)&g_xl[r3.x * C + c];
        ull e00, e01, e10, e11, e20, e21, e30, e31;
        float f;
        f = __uint_as_float(r0.y); PK2(e00, f, f);
        f = __uint_as_float(r0.z); PK2(e01, f, f);
        f = __uint_as_float(r1.y); PK2(e10, f, f);
        f = __uint_as_float(r1.z); PK2(e11, f, f);
        f = __uint_as_float(r2.y); PK2(e20, f, f);
        f = __uint_as_float(r2.z); PK2(e21, f, f);
        f = __uint_as_float(r3.y); PK2(e30, f, f);
        f = __uint_as_float(r3.z); PK2(e31, f, f);
        ull a00, a01, a10, a11, a20, a21, a30, a31;
        float p0 = lane_logit_pk(u0, xr0, xr1, e00, e01, w00, w01, w10, w11, at0, at1, c04, c06, a00, a01);
        float p1 = lane_logit_pk(u1, xr0, xr1, e10, e11, w00, w01, w10, w11, at0, at1, c04, c06, a10, a11);
        float p2 = lane_logit_pk(u2, xr0, xr1, e20, e21, w00, w01, w10, w11, at0, at1, c04, c06, a20, a21);
        float p3 = lane_logit_pk(u3, xr0, xr1, e30, e31, w00, w01, w10, w11, at0, at1, c04, c06, a30, a31);
#pragma unroll
        for (int o = 16; o; o >>= 1) {
            p0 += __shfl_xor_sync(0xffffffffu, p0, o);
            p1 += __shfl_xor_sync(0xffffffffu, p1, o);
            p2 += __shfl_xor_sync(0xffffffffu, p2, o);
            p3 += __shfl_xor_sync(0xffffffffu, p3, o);
        }
        float v0 = __expf(p0), v1 = __expf(p1), v2 = __expf(p2), v3 = __expf(p3);
        if (lane == 0) {
            g_ex[j] = v0; g_ex[j + 1] = v1; g_ex[j + 2] = v2; g_ex[j + 3] = v3;
        }
        den += (v0 + v1) + (v2 + v3);
        ull vp;
        PK2(vp, v0, v0); FMA2(acc0, vp, a00); FMA2(acc1, vp, a01);
        PK2(vp, v1, v1); FMA2(acc0, vp, a10); FMA2(acc1, vp, a11);
        PK2(vp, v2, v2); FMA2(acc0, vp, a20); FMA2(acc1, vp, a21);
        PK2(vp, v3, v3); FMA2(acc0, vp, a30); FMA2(acc1, vp, a31);
    }
    for (; j < end; j++) {
        uint4 r = g_csr[j];
        uint2 u = *(const uint2*)&g_xl[r.x * C + c];
        ull e0p, e1p, a0, a1;
        float f0 = __uint_as_float(r.y), f1 = __uint_as_float(r.z);
        PK2(e0p, f0, f0); PK2(e1p, f1, f1);
        float p = lane_logit_pk(u, xr0, xr1, e0p, e1p, w00, w01, w10, w11, at0, at1, c04, c06, a0, a1);
#pragma unroll
        for (int o = 16; o; o >>= 1) p += __shfl_xor_sync(0xffffffffu, p, o);
        float v = __expf(p);
        if (lane == 0) g_ex[j] = v;
        den += v;
        ull vp;
        PK2(vp, v, v);
        FMA2(acc0, vp, a0); FMA2(acc1, vp, a1);
    }
    float inv = 1.f / den;

    // pass B: alpha write-out, lanes parallel over edges
    for (int jj = beg + lane; jj < end; jj += 32) {
        float al = g_ex[jj] * inv;
        g_alpha[jj] = al;
        out[(long long)NN * 2 + 2LL * ET + g_csr[jj].w] = al;
    }

    float ax, ay, az, aw;
    UNPK2(ax, ay, acc0);
    UNPK2(az, aw, acc1);
    float4 bb = *(const float4*)&bgat[c];
    float hx = fmaxf(ax * inv + bb.x, 0.f);
    float hy = fmaxf(ay * inv + bb.y, 0.f);
    float hz = fmaxf(az * inv + bb.z, 0.f);
    float hw = fmaxf(aw * inv + bb.w, 0.f);
    uint2 hu;
    *(__half2*)&hu.x = __floats2half2_rn(hx, hy);
    *(__half2*)&hu.y = __floats2half2_rn(hz, hw);
    *(uint2*)&g_h[node * C + c] = hu;
}

// ---------------- K6: fused GCN gather + GEMM + head (barrier-free, gather unroll 4) ----------------
__global__ void k_gemm(const float* __restrict__ W2, const float* __restrict__ bg,
                       const float* __restrict__ W3, const float* __restrict__ b3,
                       float* __restrict__ out) {
    __shared__ float ts[64 * C];
    int lane = threadIdx.x & 31, warp = threadIdx.x >> 5;
    int rowBase = blockIdx.x * 64;
    int c = lane * 4;

    // gather phase: t[node] = sum alpha * h[src]  (deg==1 => norm==alpha)
    // each warp's 8 rows of ts are private to that warp — no block barrier needed.
#pragma unroll
    for (int i = 0; i < 8; i++) {
        int row = warp * 8 + i;
        int node = rowBase + row;
        float4 acc0 = make_float4(0.f, 0.f, 0.f, 0.f);
        float4 acc1 = make_float4(0.f, 0.f, 0.f, 0.f);
        if (node < NN) {
            int beg = g_rowptr[node], end = g_rowptr[node + 1];
            int j = beg;
            for (; j + 3 < end; j += 4) {
                int s0 = g_csr[j].x, s1 = g_csr[j + 1].x;
                int s2 = g_csr[j + 2].x, s3 = g_csr[j + 3].x;
                float al0 = g_alpha[j],     al1 = g_alpha[j + 1];
                float al2 = g_alpha[j + 2], al3 = g_alpha[j + 3];
                const float4 h0 = ldh4(&g_h[s0 * C + c]);
                const float4 h1 = ldh4(&g_h[s1 * C + c]);
                const float4 h2 = ldh4(&g_h[s2 * C + c]);
                const float4 h3 = ldh4(&g_h[s3 * C + c]);
                acc0.x += al0 * h0.x + al2 * h2.x; acc1.x += al1 * h1.x + al3 * h3.x;
                acc0.y += al0 * h0.y + al2 * h2.y; acc1.y += al1 * h1.y + al3 * h3.y;
                acc0.z += al0 * h0.z + al2 * h2.z; acc1.z += al1 * h1.z + al3 * h3.z;
                acc0.w += al0 * h0.w + al2 * h2.w; acc1.w += al1 * h1.w + al3 * h3.w;
            }
            for (; j < end; j++) {
                int s = g_csr[j].x;
                float al = g_alpha[j];
                const float4 hv = ldh4(&g_h[s * C + c]);
                acc0.x += al * hv.x;
                acc0.y += al * hv.y;
                acc0.z += al * hv.z;
                acc0.w += al * hv.w;
            }
            acc0.x += acc1.x; acc0.y += acc1.y; acc0.z += acc1.z; acc0.w += acc1.w;
        }
        *(float4*)&ts[row * C + c] = acc0;
    }
    __syncwarp();    // warp-local visibility only; warps proceed independently

    // GEMM phase: 8 rows per warp, f32x2 packed FMA
    ull acc2[8][2];
#pragma unroll
    for (int i = 0; i < 8; i++) { acc2[i][0] = 0ull; acc2[i][1] = 0ull; }

    for (int k4 = 0; k4 < C; k4 += 4) {
        ull wa[4], wb[4];
#pragma unroll
        for (int kk = 0; kk < 4; kk++) {
            float4 wv = __ldg((const float4*)&W2[(k4 + kk) * C + c]);
            PK2(wa[kk], wv.x, wv.y);
            PK2(wb[kk], wv.z, wv.w);
        }
#pragma unroll
        for (int i = 0; i < 8; i++) {
            float4 tv = *(const float4*)&ts[(warp * 8 + i) * C + k4];
            ull t0, t1, t2, t3;
            PK2(t0, tv.x, tv.x);
            PK2(t1, tv.y, tv.y);
            PK2(t2, tv.z, tv.z);
            PK2(t3, tv.w, tv.w);
            FMA2(acc2[i][0], t0, wa[0]); FMA2(acc2[i][1], t0, wb[0]);
            FMA2(acc2[i][0], t1, wa[1]); FMA2(acc2[i][1], t1, wb[1]);
            FMA2(acc2[i][0], t2, wa[2]); FMA2(acc2[i][1], t2, wb[2]);
            FMA2(acc2[i][0], t3, wa[3]); FMA2(acc2[i][1], t3, wb[3]);
        }
    }

    float4 bb  = *(const float4*)&bg[c];
    float4 w3a = *(const float4*)&W3[c * 2];
    float4 w3b = *(const float4*)&W3[c * 2 + 4];
    float b30 = b3[0], b31 = b3[1];
#pragma unroll
    for (int i = 0; i < 8; i++) {
        float a0, a1, a2, a3;
        UNPK2(a0, a1, acc2[i][0]);
        UNPK2(a2, a3, acc2[i][1]);
        float vx = fmaxf(a0 + bb.x, 0.f);
        float vy = fmaxf(a1 + bb.y, 0.f);
        float vz = fmaxf(a2 + bb.z, 0.f);
        float vw = fmaxf(a3 + bb.w, 0.f);
        float p0 = vx * w3a.x + vy * w3a.z + vz * w3b.x + vw * w3b.z;
        float p1 = vx * w3a.y + vy * w3a.w + vz * w3b.y + vw * w3b.w;
#pragma unroll
        for (int o = 16; o; o >>= 1) {
            p0 += __shfl_xor_sync(0xffffffffu, p0, o);
            p1 += __shfl_xor_sync(0xffffffffu, p1, o);
        }
        int r = rowBase + warp * 8 + i;
        if (lane == 0 && r < NN) {
            out[r * 2 + 0] = p0 + b30;
            out[r * 2 + 1] = p1 + b31;
        }
    }
}

// ---------------- launch ----------------
extern "C" void kernel_launch(void* const* d_in, const int* in_sizes, int n_in,
                              void* d_out, int out_size) {
    const float* x    = (const float*)d_in[0];
    const int*   ei   = (const int*)  d_in[1];
    const float* ew   = (const float*)d_in[2];
    const float* Wl   = (const float*)d_in[3];
    const float* bl   = (const float*)d_in[4];
    const float* Wr   = (const float*)d_in[5];
    const float* br   = (const float*)d_in[6];
    const float* We   = (const float*)d_in[7];
    const float* att  = (const float*)d_in[8];
    const float* bgat = (const float*)d_in[9];
    const float* W2   = (const float*)d_in[10];
    const float* bgcn = (const float*)d_in[11];
    const float* W3   = (const float*)d_in[12];
    const float* b3   = (const float*)d_in[13];
    float* out = (float*)d_out;

    const int TPB = 256;
    k_lin    <<<LINB + ZB, TPB>>>(x, Wl, bl, Wr, br);
    k_hist   <<<(ET + TPB - 1) / TPB, TPB>>>(ei, out);
    k_scan   <<<1, 1024>>>();
    k_scatter<<<(ET + TPB - 1) / TPB, TPB>>>(ei, ew);
    k_gat    <<<(NN * 32 + TPB - 1) / TPB, TPB>>>(We, att, bgat, out);
    k_gemm   <<<(NN + 63) / 64, TPB>>>(W2, bgcn, W3, b3, out);
}